// round 10
// baseline (speedup 1.0000x reference)
#include <cuda_runtime.h>
#include <cstdint>

typedef unsigned long long ull;

// Problem constants (fixed by setup_inputs)
#define NB 4
#define CC 128
#define HH 160
#define WW 320
#define DD 48

#define WT   128            // w-tile per CTA
#define RT   (WT + 48)      // right tile width incl. disparity halo = 176
#define CHS  16             // channels per pipeline stage
#define NSTG (CC / CHS)     // 8 stages
#define NTHR 128            // 4 warps: one per SMSP, each owns 12 disparities

#define STAGE_FLOATS (CHS * (WT + RT))     // 4864 floats = 19456 B
#define SMEM_FLOATS  (2 * STAGE_FLOATS)    // double buffer: 38912 B

__device__ __forceinline__ uint32_t smem_u32(const void* p) {
    return (uint32_t)__cvta_generic_to_shared(p);
}
// 16B async copy, global->shared, zero-fill when bytes==0 (halo padding).
__device__ __forceinline__ void cp16(uint32_t dst, const void* src, int bytes) {
    asm volatile("cp.async.cg.shared.global [%0], [%1], 16, %2;"
                 :: "r"(dst), "l"(src), "r"(bytes));
}

// packed f32x2 FMA: d.lo = a.lo*b.lo + c.lo ; d.hi = a.hi*b.hi + c.hi  (FFMA2)
__device__ __forceinline__ ull ffma2(ull a, ull b, ull c) {
    ull d;
    asm("fma.rn.f32x2 %0, %1, %2, %3;" : "=l"(d) : "l"(a), "l"(b), "l"(c));
    return d;
}
// cross-pair: returns {hi(a), lo(b)} as packed f32x2
__device__ __forceinline__ ull pk2(ull a, ull b) {
    ull r;
    asm("{\n\t"
        ".reg .b32 ax, ay, bx, by;\n\t"
        "mov.b64 {ax, ay}, %1;\n\t"
        "mov.b64 {bx, by}, %2;\n\t"
        "mov.b64 %0, {ay, bx};\n\t"
        "}" : "=l"(r) : "l"(a), "l"(b));
    return r;
}

__global__ void __launch_bounds__(NTHR, 4)
cost_volume_kernel(const float* __restrict__ left,
                   const float* __restrict__ right,
                   float* __restrict__ out)
{
    __shared__ float smem[SMEM_FLOATS];

    const int tid  = threadIdx.x;
    const int lane = tid & 31;
    const int warp = tid >> 5;          // 0..3
    const int w0   = blockIdx.x * WT;   // 0,128,256 (last tile partial)
    const int h    = blockIdx.y;
    const int n    = blockIdx.z;
    const int d0   = warp * 12;         // disparity group base

    // Rs[i] holds global w = w0-48+i. acc[dj][wi] needs R at smem index
    // ib + (wi - dj + 12), wi-dj+12 in [1,15]; ib multiple of 4 -> float4/double2 LDS.
    const int ib = 4 * lane - d0 + 36;

    const size_t chan_stride = (size_t)HH * WW;
    const float* lrow = left  + (size_t)n * CC * chan_stride + (size_t)h * WW;
    const float* rrow = right + (size_t)n * CC * chan_stride + (size_t)h * WW;

    // ---- async prefetch of one CHS-channel stage into buffer `buf` ----
    auto prefetch = [&](int c0, float* buf) {
        float* Ls = buf;                 // [CHS][WT]
        float* Rs = buf + CHS * WT;      // [CHS][RT]
        const float* lb = lrow + (size_t)c0 * chan_stride;
        const float* rb = rrow + (size_t)c0 * chan_stride;
        // L: CHS*WT/4 = 512 float4, 4 per thread
        #pragma unroll
        for (int it = 0; it < 4; it++) {
            int idx = tid + it * NTHR;       // 0..511
            int c   = idx >> 5;              // /(WT/4)
            int wq  = (idx & 31) << 2;
            int gw  = w0 + wq;
            bool ok = (gw < WW);
            const float* src = ok ? (lb + (size_t)c * chan_stride + gw) : lb;
            cp16(smem_u32(Ls + c * WT + wq), src, ok ? 16 : 0);
        }
        // R: CHS*RT/4 = 704 float4
        #pragma unroll
        for (int it = 0; it < 6; it++) {
            int idx = tid + it * NTHR;
            if (idx < CHS * (RT / 4)) {
                int c  = idx / (RT / 4);
                int wq = (idx - c * (RT / 4)) << 2;
                int gw = w0 - 48 + wq;
                bool ok = (gw >= 0) && (gw < WW);
                const float* src = ok ? (rb + (size_t)c * chan_stride + gw) : rb;
                cp16(smem_u32(Rs + c * RT + wq), src, ok ? 16 : 0);
            }
        }
        asm volatile("cp.async.commit_group;");
    };

    // packed accumulators: acc2[dj][0] = {acc[dj][w0..1]}, acc2[dj][1] = {acc[dj][w2..3]}
    ull acc2[12][2];
    #pragma unroll
    for (int j = 0; j < 12; j++) { acc2[j][0] = 0ull; acc2[j][1] = 0ull; }

    prefetch(0, smem);

    for (int s = 0; s < NSTG; s++) {
        float* cur = smem + (s & 1) * STAGE_FLOATS;
        if (s + 1 < NSTG) {
            prefetch((s + 1) * CHS, smem + ((s + 1) & 1) * STAGE_FLOATS);
            asm volatile("cp.async.wait_group 1;");   // stage s complete
        } else {
            asm volatile("cp.async.wait_group 0;");
        }
        __syncthreads();

        // ---- FFMA2 mainloop: per channel 5 LDS.128 -> 24 packed FMAs (48 flops-lanes) ----
        const float* lp = cur + 4 * lane;
        const float* rp = cur + CHS * WT + ib;
        #pragma unroll 2
        for (int c = 0; c < CHS; c++) {
            // L pairs come free from a double2 view of the float4
            double2 lv = *(const double2*)(lp + c * WT);
            ull lw01 = __double_as_longlong(lv.x);   // {l[w0], l[w1]}
            ull lw23 = __double_as_longlong(lv.y);   // {l[w2], l[w3]}

            // r window: 16 floats as 8 natural (even) pairs
            ull e[8];
            #pragma unroll
            for (int k = 0; k < 4; k++) {
                double2 rv = *(const double2*)(rp + c * RT + 4 * k);
                e[2*k]   = __double_as_longlong(rv.x);
                e[2*k+1] = __double_as_longlong(rv.y);
            }
            // odd-start pairs o[j] = {r[2j+1], r[2j+2]}
            ull o[7];
            #pragma unroll
            for (int j = 0; j < 7; j++) o[j] = pk2(e[j], e[j+1]);

            #pragma unroll
            for (int dj = 0; dj < 12; dj++) {
                const int s0 = 12 - dj;   // b-pair start for wi{0,1}
                const int s1 = 14 - dj;   // b-pair start for wi{2,3}
                ull b0 = (s0 & 1) ? o[(s0 - 1) >> 1] : e[s0 >> 1];
                ull b1 = (s1 & 1) ? o[(s1 - 1) >> 1] : e[s1 >> 1];
                acc2[dj][0] = ffma2(lw01, b0, acc2[dj][0]);
                acc2[dj][1] = ffma2(lw23, b1, acc2[dj][1]);
            }
        }
        __syncthreads();   // compute done before next prefetch overwrites this buffer
    }

    // ---- store: unpack pairs, float4 per disparity row; last tile guarded ----
    const int gw = w0 + 4 * lane;
    if (gw < WW) {
        #pragma unroll
        for (int dj = 0; dj < 12; dj++) {
            int d = d0 + dj;
            float4 v;
            asm("mov.b64 {%0, %1}, %2;" : "=f"(v.x), "=f"(v.y) : "l"(acc2[dj][0]));
            asm("mov.b64 {%0, %1}, %2;" : "=f"(v.z), "=f"(v.w) : "l"(acc2[dj][1]));
            *(float4*)(out + (((size_t)(n * DD + d) * HH + h) * WW + gw)) = v;
        }
    }
}

extern "C" void kernel_launch(void* const* d_in, const int* in_sizes, int n_in,
                              void* d_out, int out_size)
{
    const float* left  = (const float*)d_in[0];
    const float* right = (const float*)d_in[1];
    float* out = (float*)d_out;

    dim3 grid((WW + WT - 1) / WT, HH, NB);   // (3, 160, 4)
    cost_volume_kernel<<<grid, NTHR>>>(left, right, out);
}

// round 12
// speedup vs baseline: 1.3023x; 1.3023x over previous
#include <cuda_runtime.h>
#include <cuda_bf16.h>
#include <cstdint>

// Problem constants (fixed by setup_inputs)
#define NB 4
#define CC 128
#define HH 160
#define WW 320
#define DD 48
#define CHAN_STRIDE (HH * WW)

#define NTHR 256        // 8 warps, each owns 16 w-rows + its 64-wide g band
#define MT   128        // w rows per CTA tile
#define CHS  16         // channels per pipeline chunk
#define NC   (CC / CHS) // 8 chunks

// ---- smem byte layout (dynamic) ----
#define OFF_FL 0                         // fp32 L stage [2][16][128]
#define FL_B   (CHS * 128 * 4)           // 8192
#define OFF_FR (OFF_FL + 2 * FL_B)       // 16384; fp32 R stage [2][16][176]
#define FR_B   (CHS * 176 * 4)           // 11264
#define OFF_LH (OFF_FR + 2 * FR_B)       // 38912; bf16 Lh [2][16][136] (272B rows)
#define LH_B   (CHS * 136 * 2)           // 4352
#define OFF_LL (OFF_LH + 2 * LH_B)       // 47616
#define OFF_RH (OFF_LL + 2 * LH_B)       // 56320; bf16 Rh [2][16][184] (368B rows)
#define RH_B   (CHS * 184 * 2)           // 5888
#define OFF_RL (OFF_RH + 2 * RH_B)       // 68096
#define SMEM_TOTAL (OFF_RL + 2 * RH_B)   // 79872
// epilogue G[128][65] fp32 (33280 B) reuses the fp32 staging region (offset 0)
#define GSTR 65

__device__ __forceinline__ uint32_t smem_u32(const void* p) {
    return (uint32_t)__cvta_generic_to_shared(p);
}
// 16B async copy, global->shared, zero-fill when bytes==0 (halo padding).
__device__ __forceinline__ void cp16(uint32_t dst, const void* src, int bytes) {
    asm volatile("cp.async.cg.shared.global [%0], [%1], 16, %2;"
                 :: "r"(dst), "l"(src), "r"(bytes));
}
// ldmatrix 4x 8x8 b16 tiles, transposed in HW
__device__ __forceinline__ void ldsm4t(uint32_t* r, uint32_t addr) {
    asm volatile("ldmatrix.sync.aligned.m8n8.x4.trans.shared.b16 {%0,%1,%2,%3}, [%4];"
                 : "=r"(r[0]), "=r"(r[1]), "=r"(r[2]), "=r"(r[3]) : "r"(addr));
}
// D(16x8,f32) += A(16x16,bf16 row) * B(16x8,bf16 col)
__device__ __forceinline__ void mma16816(float* d, const uint32_t* a, const uint32_t* b) {
    asm volatile(
        "mma.sync.aligned.m16n8k16.row.col.f32.bf16.bf16.f32 "
        "{%0,%1,%2,%3}, {%4,%5,%6,%7}, {%8,%9}, {%0,%1,%2,%3};"
        : "+f"(d[0]), "+f"(d[1]), "+f"(d[2]), "+f"(d[3])
        : "r"(a[0]), "r"(a[1]), "r"(a[2]), "r"(a[3]), "r"(b[0]), "r"(b[1]));
}
// fp32 pair (w, w+1) -> hi/lo bf16x2 words (low 16 bits = first element)
__device__ __forceinline__ void split_pair(float a, float b, uint32_t& hi, uint32_t& lo) {
    __nv_bfloat162 h2 = __floats2bfloat162_rn(a, b);
    hi = *reinterpret_cast<uint32_t*>(&h2);
    float ra = a - __bfloat162float(h2.x);
    float rb = b - __bfloat162float(h2.y);
    __nv_bfloat162 l2 = __floats2bfloat162_rn(ra, rb);
    lo = *reinterpret_cast<uint32_t*>(&l2);
}

__global__ void __launch_bounds__(NTHR, 2)
cost_volume_mma_kernel(const float* __restrict__ left,
                       const float* __restrict__ right,
                       float* __restrict__ out)
{
    extern __shared__ char sm[];
    const uint32_t smb = smem_u32(sm);
    const int tid  = threadIdx.x;
    const int lane = tid & 31;
    const int wid  = tid >> 5;            // 0..7
    const int i0   = wid * 16;            // warp's w-rows i0..i0+15; g-band [i0, i0+64)
    const int w0   = blockIdx.x * MT;     // 0,128,256 (last tile zero-padded)
    const int h    = blockIdx.y;
    const int n    = blockIdx.z;

    const float* lrow = left  + (size_t)n * CC * CHAN_STRIDE + (size_t)h * WW;
    const float* rrow = right + (size_t)n * CC * CHAN_STRIDE + (size_t)h * WW;

    // ---- cp.async stage of one 16-channel chunk (fp32) ----
    auto cp_stage = [&](int s, int buf) {
        const float* lb = lrow + (size_t)(s * CHS) * CHAN_STRIDE;
        const float* rb = rrow + (size_t)(s * CHS) * CHAN_STRIDE;
        #pragma unroll
        for (int it = 0; it < 2; it++) {           // L: 512 float4
            int idx = tid + it * NTHR;
            int c = idx >> 5, q = idx & 31;
            int gw = w0 + 4 * q;
            bool ok = (gw < WW);
            cp16(smb + OFF_FL + buf * FL_B + c * 512 + 16 * q,
                 ok ? lb + (size_t)c * CHAN_STRIDE + gw : lb, ok ? 16 : 0);
        }
        #pragma unroll
        for (int it = 0; it < 3; it++) {           // R: 704 float4
            int idx = tid + it * NTHR;
            if (idx < CHS * 44) {
                int c = idx / 44, q = idx - c * 44;
                int gw = w0 - 48 + 4 * q;
                bool ok = (gw >= 0) && (gw < WW);
                cp16(smb + OFF_FR + buf * FR_B + c * 704 + 16 * q,
                     ok ? rb + (size_t)c * CHAN_STRIDE + gw : rb, ok ? 16 : 0);
            }
        }
        asm volatile("cp.async.commit_group;");
    };

    // ---- convert fp32 chunk -> bf16 hi/lo tiles (padded strides) ----
    auto convert = [&](int buf) {
        const float* Lf = (const float*)(sm + OFF_FL + buf * FL_B);
        const float* Rf = (const float*)(sm + OFF_FR + buf * FR_B);
        char* lh = sm + OFF_LH + buf * LH_B;
        char* ll = sm + OFF_LL + buf * LH_B;
        char* rh = sm + OFF_RH + buf * RH_B;
        char* rl = sm + OFF_RL + buf * RH_B;
        #pragma unroll
        for (int it = 0; it < 4; it++) {           // L: 1024 fp32 pairs
            int idx = tid + it * NTHR;
            int c = idx >> 6, p = idx & 63;
            float2 v = *(const float2*)(Lf + c * 128 + 2 * p);
            uint32_t hi, lo; split_pair(v.x, v.y, hi, lo);
            *(uint32_t*)(lh + c * 272 + 4 * p) = hi;
            *(uint32_t*)(ll + c * 272 + 4 * p) = lo;
        }
        #pragma unroll
        for (int it = 0; it < 6; it++) {           // R: 1408 fp32 pairs
            int idx = tid + it * NTHR;
            if (idx < CHS * 88) {
                int c = idx / 88, p = idx - c * 88;
                float2 v = *(const float2*)(Rf + c * 176 + 2 * p);
                uint32_t hi, lo; split_pair(v.x, v.y, hi, lo);
                *(uint32_t*)(rh + c * 368 + 4 * p) = hi;
                *(uint32_t*)(rl + c * 368 + 4 * p) = lo;
            }
        }
    };

    // per-lane ldmatrix address offsets (matrix m = lane>>3, row r = lane&7)
    const int mat = lane >> 3, r8 = lane & 7;
    // A tiles [k][i]: mats (i0,k0-7),(i0+8,k0-7),(i0,k8-15),(i0+8,k8-15)
    const uint32_t a_off = (uint32_t)((r8 + 8 * (mat >> 1)) * 272 + (i0 + 8 * (mat & 1)) * 2);
    // B tiles [k][g]: mats (k0-7,g),(k8-15,g),(k0-7,g+8),(k8-15,g+8); g base = i0
    const uint32_t b_off = (uint32_t)((r8 + 8 * (mat & 1)) * 368 + (i0 + 8 * (mat >> 1)) * 2);

    float acc[8][4];
    #pragma unroll
    for (int j = 0; j < 8; j++)
        #pragma unroll
        for (int q = 0; q < 4; q++) acc[j][q] = 0.0f;

    // ---- 24 HMMAs per warp per chunk: 3 split terms x 8 n-frags ----
    auto compute = [&](int buf) {
        uint32_t ah[4], al[4];
        ldsm4t(ah, smb + OFF_LH + buf * LH_B + a_off);
        ldsm4t(al, smb + OFF_LL + buf * LH_B + a_off);
        uint32_t rhb = smb + OFF_RH + buf * RH_B + b_off;
        uint32_t rlb = smb + OFF_RL + buf * RH_B + b_off;
        #pragma unroll
        for (int jb = 0; jb < 4; jb++) {           // 16 g-cols per jb (2 n-frags)
            uint32_t bh[4], bl[4];
            ldsm4t(bh, rhb + jb * 32);
            ldsm4t(bl, rlb + jb * 32);
            mma16816(acc[2 * jb],     ah, bh);
            mma16816(acc[2 * jb],     ah, bl);
            mma16816(acc[2 * jb],     al, bh);
            mma16816(acc[2 * jb + 1], ah, bh + 2);
            mma16816(acc[2 * jb + 1], ah, bl + 2);
            mma16816(acc[2 * jb + 1], al, bh + 2);
        }
    };

    // ================= main pipeline =================
    cp_stage(0, 0);
    for (int s = 0; s < NC; s++) {
        int buf = s & 1;
        if (s + 1 < NC) {
            cp_stage(s + 1, buf ^ 1);
            asm volatile("cp.async.wait_group 1;");
        } else {
            asm volatile("cp.async.wait_group 0;");
        }
        __syncthreads();        // all threads' cp for chunk s landed
        convert(buf);
        __syncthreads();        // bf16 tiles visible to all warps
        compute(buf);
    }

    // ---- epilogue: frags -> smem G[128][65] -> coalesced band stores ----
    float* Gs = (float*)sm;     // overlaps dead fp32 staging region
    {
        int gid = lane >> 2, t4 = lane & 3;
        int ro = (i0 + gid) * GSTR, c0 = 2 * t4;
        #pragma unroll
        for (int j = 0; j < 8; j++) {
            Gs[ro + 8 * j + c0]                 = acc[j][0];
            Gs[ro + 8 * j + c0 + 1]             = acc[j][1];
            Gs[ro + 8 * GSTR + 8 * j + c0]      = acc[j][2];
            Gs[ro + 8 * GSTR + 8 * j + c0 + 1]  = acc[j][3];
        }
    }
    __syncthreads();
    {
        int i  = tid & 127;
        int dh = (tid >> 7) * 24;
        if (w0 + i < WW) {
            #pragma unroll
            for (int dj = 0; dj < 24; dj++) {
                int d = dh + dj;    // g - i0 = (i&15) + 48 - d
                out[(((size_t)(n * DD + d)) * HH + h) * WW + w0 + i] =
                    Gs[i * GSTR + (i & 15) + 48 - d];
            }
        }
    }
}

extern "C" void kernel_launch(void* const* d_in, const int* in_sizes, int n_in,
                              void* d_out, int out_size)
{
    const float* left  = (const float*)d_in[0];
    const float* right = (const float*)d_in[1];
    float* out = (float*)d_out;

    cudaFuncSetAttribute(cost_volume_mma_kernel,
                         cudaFuncAttributeMaxDynamicSharedMemorySize, SMEM_TOTAL);

    dim3 grid((WW + MT - 1) / MT, HH, NB);   // (3, 160, 4)
    cost_volume_mma_kernel<<<grid, NTHR, SMEM_TOTAL>>>(left, right, out);
}